// round 2
// baseline (speedup 1.0000x reference)
#include <cuda_runtime.h>
#include <cuda_bf16.h>

// Scatter-add: out[dst[e]] += edge_attr[e] * x[src[e]],  D=64 f32 per row.
// edge_index is INT32 (JAX x64 disabled downcasts the declared int64).
// 16 threads per edge, one float4 (16B) per thread -> 4 coalesced sectors
// per gathered row, and one red.global.add.v4.f32 per thread (no RMW
// round trip).

__global__ void _zero_out_kernel(float4* __restrict__ out, int n4) {
    int i = blockIdx.x * blockDim.x + threadIdx.x;
    if (i < n4) out[i] = make_float4(0.f, 0.f, 0.f, 0.f);
}

__global__ void __launch_bounds__(256)
_scatter_add_kernel(const float4* __restrict__ x4,      // x viewed as [N,16] float4
                    const int* __restrict__ src,        // edge_index row 0 (int32)
                    const int* __restrict__ dst,        // edge_index row 1 (int32)
                    const float* __restrict__ attr,     // [E]
                    float* __restrict__ out,            // [n_coarse, 64]
                    int num_edges,
                    int n_nodes,
                    int n_coarse) {
    int t = blockIdx.x * blockDim.x + threadIdx.x;
    int e = t >> 4;          // edge id
    int c = t & 15;          // float4 chunk within the 64-float row
    if (e >= num_edges) return;

    int s = src[e];
    int d = dst[e];
    float w = attr[e];

    // Safety net: if the dtype assumption is ever wrong this turns a crash
    // into a visible rel_err failure. Two predicated compares, ~free.
    if ((unsigned)s >= (unsigned)n_nodes || (unsigned)d >= (unsigned)n_coarse)
        return;

    float4 v = x4[(long long)s * 16 + c];
    v.x *= w; v.y *= w; v.z *= w; v.w *= w;

    float* p = out + (long long)d * 64 + c * 4;   // 16B-aligned (row stride 256B)
    asm volatile("red.global.add.v4.f32 [%0], {%1, %2, %3, %4};"
                 :: "l"(p), "f"(v.x), "f"(v.y), "f"(v.z), "f"(v.w)
                 : "memory");
}

extern "C" void kernel_launch(void* const* d_in, const int* in_sizes, int n_in,
                              void* d_out, int out_size) {
    const float4* x4   = (const float4*)d_in[0];     // [100000*64] f32
    const int*    eidx = (const int*)d_in[1];        // [2, E] int32
    const float*  attr = (const float*)d_in[2];      // [E] f32
    float*        out  = (float*)d_out;              // [n_coarse*64] f32

    int num_edges = in_sizes[2];                     // E from edge_attr count
    int n_nodes   = in_sizes[0] / 64;                // x rows
    int n_coarse  = out_size / 64;                   // output rows
    const int* src = eidx;
    const int* dst = eidx + num_edges;

    // 1) zero the (poisoned) output
    int n4 = out_size / 4;
    int zblocks = (n4 + 255) / 256;
    _zero_out_kernel<<<zblocks, 256>>>((float4*)out, n4);

    // 2) weighted scatter-add, 16 threads/edge
    long long total_threads = (long long)num_edges * 16;
    int sblocks = (int)((total_threads + 255) / 256);
    _scatter_add_kernel<<<sblocks, 256>>>(x4, src, dst, attr, out,
                                          num_edges, n_nodes, n_coarse);
}